// round 9
// baseline (speedup 1.0000x reference)
#include <cuda_runtime.h>
#include <cstdint>

#define B_   256
#define T_   128
#define IN_  128
#define H_   256
#define H3_  768
#define OUT_ 128

// ---- persistent recurrence: 16 clusters x 8 CTAs; Wh resident in SMEM
#define CL   8                     // CTAs per cluster
#define RWS  48                    // (c,b) state rows per cluster
#define NBLK 128                   // total CTAs
#define PTH  128                   // g=tid>>5 -> rows 12g..12g+11; u=tid&31 -> col u per segment
#define NCOL 96                    // gate columns per CTA (3 segments of 32)
#define HSTR 52                    // hst column stride (48 rows + pad; 16B-aligned)
#define WHS_FLOATS (H_*NCOL)       // 24576 (96KB Wh slice, resident)
#define HST_FLOATS (H_*HSTR)       // 13312
#define GXS_FLOATS (RWS*NCOL)      // 4608
#define GX_BYTES   (GXS_FLOATS*4)  // 18432
#define SMEM_FLOATS (WHS_FLOATS + 2*HST_FLOATS + GXS_FLOATS)   // 55808
#define SMEM_BYTES  (SMEM_FLOATS*4 + 16)                       // 223248

// scratch (device globals: allocation-free)
__device__ float g_Wh3[CL * WHS_FLOATS];            // [q][k][s*32+l] reordered Wh slices
__device__ float g_gx3[(size_t)CL * T_ * B_ * NCOL];// [q][t][b][s*32+l] x@Wx+bx
__device__ float g_hT[3 * B_ * H_];                 // final hidden state

// ---------------------------------------------------------------- helpers
static __device__ __forceinline__ uint32_t s2u(const void* p) {
    uint32_t a;
    asm("{ .reg .u64 t; cvta.to.shared.u64 t, %1; cvt.u32.u64 %0, t; }"
        : "=r"(a) : "l"(p));
    return a;
}
static __device__ __forceinline__ void mbar_init(uint32_t m, int cnt) {
    asm volatile("mbarrier.init.shared.b64 [%0], %1;" :: "r"(m), "r"(cnt) : "memory");
}
static __device__ __forceinline__ void mbar_expect(uint32_t m, uint32_t bytes) {
    asm volatile("mbarrier.arrive.expect_tx.shared.b64 _, [%0], %1;"
                 :: "r"(m), "r"(bytes) : "memory");
}
static __device__ __forceinline__ void mbar_wait(uint32_t m, int ph) {
    asm volatile(
        "{\n\t"
        ".reg .pred P;\n\t"
        "WL%=:\n\t"
        "mbarrier.try_wait.parity.acquire.cta.shared::cta.b64 P, [%0], %1;\n\t"
        "@P bra WD%=;\n\t"
        "bra WL%=;\n\t"
        "WD%=:\n\t"
        "}"
        :: "r"(m), "r"(ph) : "memory");
}
static __device__ __forceinline__ void bulk_g2s(uint32_t dst, const void* src,
                                                uint32_t bytes, uint32_t m) {
    asm volatile(
        "cp.async.bulk.shared::cluster.global.mbarrier::complete_tx::bytes [%0], [%1], %2, [%3];"
        :: "r"(dst), "l"(src), "r"(bytes), "r"(m) : "memory");
}
static __device__ __forceinline__ void fence_async() {
    asm volatile("fence.proxy.async.shared::cta;" ::: "memory");
}
static __device__ __forceinline__ uint32_t mapa_u32(uint32_t addr, uint32_t rank) {
    uint32_t r;
    asm("mapa.shared::cluster.u32 %0, %1, %2;" : "=r"(r) : "r"(addr), "r"(rank));
    return r;
}
static __device__ __forceinline__ void st_cluster_v4(uint32_t addr, float a, float b,
                                                     float c, float d) {
    asm volatile("st.shared::cluster.v4.b32 [%0], {%1, %2, %3, %4};"
                 :: "r"(addr), "f"(a), "f"(b), "f"(c), "f"(d) : "memory");
}
#define CLUSTER_ARRIVE() asm volatile("barrier.cluster.arrive.aligned;" ::: "memory")
#define CLUSTER_WAIT()   asm volatile("barrier.cluster.wait.aligned;"   ::: "memory")

// packed fp32x2 ops
static __device__ __forceinline__ uint64_t pack2(float v) {
    uint64_t r;
    asm("mov.b64 %0, {%1, %1};" : "=l"(r) : "f"(v));
    return r;
}
static __device__ __forceinline__ void fma2(uint64_t& d, uint64_t a, uint64_t b) {
    asm("fma.rn.f32x2 %0, %1, %2, %0;" : "+l"(d) : "l"(a), "l"(b));
}
static __device__ __forceinline__ float f32x2_lo(uint64_t v) {
    return __uint_as_float((uint32_t)v);
}
static __device__ __forceinline__ float f32x2_hi(uint64_t v) {
    return __uint_as_float((uint32_t)(v >> 32));
}
static __device__ __forceinline__ float sigmoidf_(float x) {
    return __fdividef(1.0f, 1.0f + __expf(-x));
}
static __device__ __forceinline__ float tanhf_(float x) {
    float ax = fabsf(x);
    float t  = __expf(-2.0f * ax);
    float r  = __fdividef(1.0f - t, 1.0f + t);
    return x >= 0.0f ? r : -r;
}

// ---------------------------------------------------------------- Wh reorder
// g_Wh3[q][k][s*32+l] = Wh[k][s*256 + q*32 + l]
__global__ void __launch_bounds__(256) k_prep(const float* __restrict__ Wh) {
    const int e = blockIdx.x * 256 + threadIdx.x;    // 0..196607
    const int q = e / WHS_FLOATS;
    const int rem = e - q * WHS_FLOATS;
    const int k = rem / NCOL;
    const int c = rem - k * NCOL;
    const int s = c >> 5, l = c & 31;
    g_Wh3[e] = Wh[k * H3_ + s * 256 + q * 32 + l];
}

// ---------------------------------------------------------------- gx = x @ Wx + bx  (FFMA2)
// Output per-q-slice: g_gx3[q][m][s*32+l], m = t*256+b.
__global__ void __launch_bounds__(256) k_gx(const float* __restrict__ x,
                                            const float* __restrict__ Wx,
                                            const float* __restrict__ bx) {
    __shared__ float As[16 * 66];
    __shared__ float Bs[16 * 64];
    const int tid = threadIdx.x;
    const int tx = tid & 15, ty = tid >> 4;
    const int n0 = blockIdx.x * 64;
    const int m0 = blockIdx.y * 64;

    uint64_t acc2[2][4];
#pragma unroll
    for (int p = 0; p < 2; p++)
#pragma unroll
        for (int c = 0; c < 4; c++) acc2[p][c] = 0ULL;

    for (int k0 = 0; k0 < IN_; k0 += 16) {
#pragma unroll
        for (int i = 0; i < 4; i++) {
            int e  = tid + i * 256;
            int mm = e >> 4, kk = e & 15;
            int m  = m0 + mm;
            int tt = m >> 8, bb = m & 255;
            As[kk * 66 + mm] = x[bb * (T_ * IN_) + tt * IN_ + k0 + kk];
        }
#pragma unroll
        for (int i = 0; i < 4; i++) {
            int e  = tid + i * 256;
            int kk = e >> 6, nn = e & 63;
            Bs[kk * 64 + nn] = Wx[(k0 + kk) * H3_ + n0 + nn];
        }
        __syncthreads();
#pragma unroll
        for (int kk = 0; kk < 16; kk++) {
            uint64_t a01 = *(const uint64_t*)&As[kk * 66 + ty * 4];
            uint64_t a23 = *(const uint64_t*)&As[kk * 66 + ty * 4 + 2];
            float4 b4 = *(const float4*)&Bs[kk * 64 + tx * 4];
            uint64_t p0 = pack2(b4.x), p1 = pack2(b4.y);
            uint64_t p2 = pack2(b4.z), p3 = pack2(b4.w);
            fma2(acc2[0][0], a01, p0); fma2(acc2[0][1], a01, p1);
            fma2(acc2[0][2], a01, p2); fma2(acc2[0][3], a01, p3);
            fma2(acc2[1][0], a23, p0); fma2(acc2[1][1], a23, p1);
            fma2(acc2[1][2], a23, p2); fma2(acc2[1][3], a23, p3);
        }
        __syncthreads();
    }
    const int n = n0 + tx * 4;           // 4 consecutive cols: same q, same segment
    const int q = (n >> 5) & 7;
    const int c96 = (n >> 8) * 32 + (n & 31);
    float4 bxv = *(const float4*)&bx[n];
    float* dst = g_gx3 + (size_t)q * ((size_t)T_ * B_ * NCOL) + c96;
#pragma unroll
    for (int p = 0; p < 2; p++) {
        float4 lo4, hi4;
        lo4.x = f32x2_lo(acc2[p][0]) + bxv.x;  hi4.x = f32x2_hi(acc2[p][0]) + bxv.x;
        lo4.y = f32x2_lo(acc2[p][1]) + bxv.y;  hi4.y = f32x2_hi(acc2[p][1]) + bxv.y;
        lo4.z = f32x2_lo(acc2[p][2]) + bxv.z;  hi4.z = f32x2_hi(acc2[p][2]) + bxv.z;
        lo4.w = f32x2_lo(acc2[p][3]) + bxv.w;  hi4.w = f32x2_hi(acc2[p][3]) + bxv.w;
        *(float4*)(dst + (size_t)(m0 + ty * 4 + 2 * p)     * NCOL) = lo4;
        *(float4*)(dst + (size_t)(m0 + ty * 4 + 2 * p + 1) * NCOL) = hi4;
    }
}

// ---------------------------------------------------------------- persistent CRU recurrence
// 16 clusters x 8 CTAs. Cluster owns 48 rows; CTA q owns gate cols {32q+u} in each
// of the 3 segments, with its 96-col Wh slice RESIDENT in SMEM (no streaming).
// h double-buffered in SMEM [k][r]; each CTA pushes its 32 updated h-columns to all
// 8 cluster CTAs via st.shared::cluster.v4. Own-k-chunk first + split cluster
// barrier hides the exchange. Thread tile: 12 rows x 3 cols (128 threads).
__global__ void __launch_bounds__(PTH) __cluster_dims__(CL, 1, 1)
k_cru(const float* __restrict__ h0, const float* __restrict__ bh) {
    extern __shared__ float sm[];
    float* whs  = sm;                                   // [256][96] Wh slice (resident)
    float* hst0 = sm + WHS_FLOATS;                      // [256][HSTR] h buffer 0
    float* hst1 = hst0 + HST_FLOATS;                    // [256][HSTR] h buffer 1
    float* gxs  = hst1 + HST_FLOATS;                    // [48][96] gx tile
    uint64_t* mb = (uint64_t*)(sm + SMEM_FLOATS);       // whs + gx barriers

    const int tid = threadIdx.x;
    const int g   = tid >> 5;           // 0..3 -> rows 12g..12g+11
    const int u   = tid & 31;           // owned col u per segment
    const int q   = blockIdx.x & 7;     // cluster rank
    const int cl  = blockIdx.x >> 3;
    const int r0  = cl * RWS;
    const int b_base = r0 & (B_ - 1);
    const int jh  = q * 32 + u;         // owned h column

    const uint32_t mbw = s2u(mb), mbg = s2u(mb + 1);
    const uint32_t gxsu = s2u(gxs);
    const uint32_t h0u = s2u(hst0), h1u = s2u(hst1);
    uint32_t p0[CL], p1[CL];
#pragma unroll
    for (int r = 0; r < CL; r++) {
        p0[r] = mapa_u32(h0u, r);
        p1[r] = mapa_u32(h1u, r);
    }
    const float* gxq = g_gx3 + (size_t)q * ((size_t)T_ * B_ * NCOL);

    if (tid == 0) {
        mbar_init(mbw, 1);
        mbar_init(mbg, 1);
        fence_async();
    }
    __syncthreads();

    if (tid == 0) {
        mbar_expect(mbw, WHS_FLOATS * 4);
        bulk_g2s(s2u(whs), g_Wh3 + q * WHS_FLOATS, WHS_FLOATS * 4, mbw);
        const int n1 = (b_base + RWS > B_) ? (B_ - b_base) : RWS;
        mbar_expect(mbg, GX_BYTES);
        bulk_g2s(gxsu, gxq + (size_t)b_base * NCOL, n1 * NCOL * 4, mbg);
        if (n1 < RWS)
            bulk_g2s(gxsu + n1 * NCOL * 4, gxq, (RWS - n1) * NCOL * 4, mbg);
    }

    // initial h: full 48x256 tile, transposed: hst0[k*HSTR + r]
    for (int idx = tid; idx < RWS * H_; idx += PTH) {
        const int r = idx >> 8, k = idx & 255;
        hst0[k * HSTR + r] = h0[(r0 + r) * H_ + k];
    }

    uint64_t bh2[3];
#pragma unroll
    for (int s = 0; s < 3; s++) bh2[s] = pack2(bh[s * H_ + jh]);

    __syncthreads();
    CLUSTER_ARRIVE();          // pairs with t=0's wait at i==1
    mbar_wait(mbw, 0);         // Wh slice resident

    int phg = 0;

    for (int t = 0; t < T_; t++) {
        const float* hcur = (t & 1) ? hst1 : hst0;
        const int nb = (t & 1) ? 0 : 1;       // next-buffer id

        uint64_t acc[6][3];
#pragma unroll
        for (int p = 0; p < 6; p++)
#pragma unroll
            for (int s = 0; s < 3; s++) acc[p][s] = bh2[s];

        // GEMM: gh = h @ Wh_slice; own k-chunk (k in [32q,32q+32)) first
        for (int i = 0; i < CL; i++) {
            if (i == 1) CLUSTER_WAIT();       // peer h columns needed from here
            const int kb = ((q + i) & 7) * 32;
            const float* hp = hcur + kb * HSTR + 12 * g;
            const float* bp = whs + kb * NCOL + u;
#pragma unroll 4
            for (int kk = 0; kk < 32; kk++) {
                uint64_t a0 = *(const uint64_t*)(hp + kk * HSTR + 0);
                uint64_t a1 = *(const uint64_t*)(hp + kk * HSTR + 2);
                uint64_t a2 = *(const uint64_t*)(hp + kk * HSTR + 4);
                uint64_t a3 = *(const uint64_t*)(hp + kk * HSTR + 6);
                uint64_t a4 = *(const uint64_t*)(hp + kk * HSTR + 8);
                uint64_t a5 = *(const uint64_t*)(hp + kk * HSTR + 10);
                uint64_t b0 = pack2(bp[kk * NCOL]);
                uint64_t b1 = pack2(bp[kk * NCOL + 32]);
                uint64_t b2 = pack2(bp[kk * NCOL + 64]);
                fma2(acc[0][0], a0, b0); fma2(acc[0][1], a0, b1); fma2(acc[0][2], a0, b2);
                fma2(acc[1][0], a1, b0); fma2(acc[1][1], a1, b1); fma2(acc[1][2], a1, b2);
                fma2(acc[2][0], a2, b0); fma2(acc[2][1], a2, b1); fma2(acc[2][2], a2, b2);
                fma2(acc[3][0], a3, b0); fma2(acc[3][1], a3, b1); fma2(acc[3][2], a3, b2);
                fma2(acc[4][0], a4, b0); fma2(acc[4][1], a4, b1); fma2(acc[4][2], a4, b2);
                fma2(acc[5][0], a5, b0); fma2(acc[5][1], a5, b1); fma2(acc[5][2], a5, b2);
            }
        }

        // gate epilogue: 12 h-values for col jh, rows 12g..12g+11
        mbar_wait(mbg, phg); phg ^= 1;
        float nv[12];
#pragma unroll
        for (int p = 0; p < 6; p++) {
#pragma unroll
            for (int c = 0; c < 2; c++) {
                const int R = 12 * g + 2 * p + c;
                const float hr = c ? f32x2_hi(acc[p][0]) : f32x2_lo(acc[p][0]);
                const float hz = c ? f32x2_hi(acc[p][1]) : f32x2_lo(acc[p][1]);
                const float hn = c ? f32x2_hi(acc[p][2]) : f32x2_lo(acc[p][2]);
                const float xr = gxs[R * NCOL + u];
                const float xz = gxs[R * NCOL + 32 + u];
                const float xn = gxs[R * NCOL + 64 + u];
                const float rg = sigmoidf_(xr + hr);
                const float zg = sigmoidf_(xz + hz);
                const float ng = tanhf_(xn + rg * hn);
                const float ho = hcur[jh * HSTR + R];
                nv[2 * p + c] = ng + zg * (ho - ng);
            }
        }

        // push h(next) col jh to all 8 cluster CTAs (self included)
        const uint32_t off = (uint32_t)(jh * HSTR + 12 * g) * 4u;
#pragma unroll
        for (int r = 0; r < CL; r++) {
            const uint32_t base = (nb ? p1[r] : p0[r]) + off;
            st_cluster_v4(base,      nv[0], nv[1], nv[2],  nv[3]);
            st_cluster_v4(base + 16, nv[4], nv[5], nv[6],  nv[7]);
            st_cluster_v4(base + 32, nv[8], nv[9], nv[10], nv[11]);
        }

        __syncthreads();   // local h writes visible; gxs fully consumed

        if (tid == 0 && t + 1 < T_) {
            const int n1 = (b_base + RWS > B_) ? (B_ - b_base) : RWS;
            mbar_expect(mbg, GX_BYTES);
            bulk_g2s(gxsu, gxq + ((size_t)(t + 1) * B_ + b_base) * NCOL,
                     n1 * NCOL * 4, mbg);
            if (n1 < RWS)
                bulk_g2s(gxsu + n1 * NCOL * 4, gxq + (size_t)(t + 1) * B_ * NCOL,
                         (RWS - n1) * NCOL * 4, mbg);
        }

        CLUSTER_ARRIVE();  // releases peer pushes; consumed at next step's i==1
    }

    CLUSTER_WAIT();        // drain final phase; in-flight peer stores complete

    // final h is in hst0 (t=127 wrote buffer 0); store own column
#pragma unroll 4
    for (int p = 0; p < 12; p++) {
        const int r = 12 * g + p;
        g_hT[(r0 + r) * H_ + jh] = hst0[jh * HSTR + r];
    }
}

// ---------------------------------------------------------------- out = elu((sum_c hT) @ Wf + bf)
__global__ void __launch_bounds__(128) k_out(const float* __restrict__ Wf,
                                             const float* __restrict__ bf,
                                             float* __restrict__ out) {
    __shared__ float s[H_];
    const int b = blockIdx.x;
    const int tid = threadIdx.x;
    for (int k = tid; k < H_; k += 128)
        s[k] = g_hT[b * H_ + k] + g_hT[B_ * H_ + b * H_ + k] + g_hT[2 * B_ * H_ + b * H_ + k];
    __syncthreads();
    float acc = bf[tid];
#pragma unroll 8
    for (int k = 0; k < H_; k++)
        acc = fmaf(s[k], Wf[k * OUT_ + tid], acc);
    out[b * OUT_ + tid] = acc > 0.0f ? acc : expm1f(acc);
}

// ---------------------------------------------------------------- feature = mean_b hT -> (3, H)
__global__ void __launch_bounds__(256) k_feat(float* __restrict__ feat) {
    __shared__ float p[8][32];
    const int tx = threadIdx.x & 31, ty = threadIdx.x >> 5;
    const int jg = blockIdx.x * 32 + tx;            // 0..767
    const int c = jg >> 8, j = jg & 255;
    float s = 0.0f;
#pragma unroll 8
    for (int i = 0; i < 32; i++) {
        const int b = ty * 32 + i;
        s += g_hT[c * (B_ * H_) + b * H_ + j];
    }
    p[ty][tx] = s;
    __syncthreads();
    if (ty == 0) {
        float acc = 0.0f;
#pragma unroll
        for (int qq = 0; qq < 8; qq++) acc += p[qq][tx];
        feat[jg] = acc * (1.0f / 256.0f);
    }
}

// ---------------------------------------------------------------- launch
extern "C" void kernel_launch(void* const* d_in, const int* in_sizes, int n_in,
                              void* d_out, int out_size) {
    const float* x  = (const float*)d_in[0];
    const float* h0 = (const float*)d_in[1];
    const float* Wx = (const float*)d_in[2];
    const float* bx = (const float*)d_in[3];
    const float* Wh = (const float*)d_in[4];
    const float* bh = (const float*)d_in[5];
    const float* Wf = (const float*)d_in[6];
    const float* bf = (const float*)d_in[7];
    float* out = (float*)d_out;

    cudaFuncSetAttribute(k_cru, cudaFuncAttributeMaxDynamicSharedMemorySize, SMEM_BYTES);

    k_prep<<<CL * WHS_FLOATS / 256, 256>>>(Wh);
    dim3 g1(H3_ / 64, (T_ * B_) / 64);   // (12, 512)
    k_gx<<<g1, 256>>>(x, Wx, bx);
    k_cru<<<NBLK, PTH, SMEM_BYTES>>>(h0, bh);
    k_out<<<B_, 128>>>(Wf, bf, out);
    k_feat<<<24, 256>>>(out + (out_size - 3 * H_));
}

// round 10
// speedup vs baseline: 1.8272x; 1.8272x over previous
#include <cuda_runtime.h>
#include <cstdint>

#define B_   256
#define T_   128
#define IN_  128
#define H_   256
#define H3_  768
#define OUT_ 128

// ---- persistent recurrence: 64 clusters x 2 CTAs, 12 rows per cluster
#define RWS  12                    // (c,b) state rows per cluster
#define NBLK 128                   // CTAs (64 clusters of 2)
#define PTH  128                   // wg = tid>>6 -> rows 6wg..6wg+5; u = tid&63 -> col pair 2u,2u+1
#define NCOL 384                   // gate columns per CTA (3 segments of 128)
#define KC   32                    // k rows of Wh per chunk
#define NCHUNK (H_/KC)             // 8
#define NBUF 3
#define CHUNK_BYTES (KC*NCOL*4)    // 49152
#define GX_BYTES (RWS*NCOL*4)      // 18432
#define HSTR 28                    // h column stride: 24 duplicated floats + 4 pad (16B-aligned groups)
#define HST_FLOATS (H_*HSTR)       // 7168
#define BS_FLOATS  (NBUF*KC*NCOL)  // 36864
#define GXS_FLOATS (RWS*NCOL)      // 4608
#define SMEM_FLOATS (2*HST_FLOATS + BS_FLOATS + GXS_FLOATS)   // 55808
#define SMEM_BYTES  (SMEM_FLOATS*4 + 64)                      // 223296

#define WH2_HALF (H_*NCOL)             // 98304 floats per half
#define GX2_HALF ((size_t)T_*B_*NCOL)  // 12.58M floats per half

// scratch (device globals: allocation-free)
__device__ float g_Wh2[2 * WH2_HALF];            // [q][k][s*128+l] reordered Wh
__device__ float g_gx2[2 * GX2_HALF];            // [q][t*256+b][384] x@Wx+bx+bh, per-half cols
__device__ float g_hT[3 * B_ * H_];              // final hidden state

// ---------------------------------------------------------------- helpers
static __device__ __forceinline__ uint32_t s2u(const void* p) {
    uint32_t a;
    asm("{ .reg .u64 t; cvta.to.shared.u64 t, %1; cvt.u32.u64 %0, t; }"
        : "=r"(a) : "l"(p));
    return a;
}
static __device__ __forceinline__ void mbar_init(uint32_t m, int cnt) {
    asm volatile("mbarrier.init.shared.b64 [%0], %1;" :: "r"(m), "r"(cnt) : "memory");
}
static __device__ __forceinline__ void mbar_expect(uint32_t m, uint32_t bytes) {
    asm volatile("mbarrier.arrive.expect_tx.shared.b64 _, [%0], %1;"
                 :: "r"(m), "r"(bytes) : "memory");
}
static __device__ __forceinline__ void mbar_wait(uint32_t m, int ph) {
    asm volatile(
        "{\n\t"
        ".reg .pred P;\n\t"
        "WL%=:\n\t"
        "mbarrier.try_wait.parity.acquire.cta.shared::cta.b64 P, [%0], %1;\n\t"
        "@P bra WD%=;\n\t"
        "bra WL%=;\n\t"
        "WD%=:\n\t"
        "}"
        :: "r"(m), "r"(ph) : "memory");
}
static __device__ __forceinline__ void bulk_g2s(uint32_t dst, const void* src,
                                                uint32_t bytes, uint32_t m) {
    asm volatile(
        "cp.async.bulk.shared::cluster.global.mbarrier::complete_tx::bytes [%0], [%1], %2, [%3];"
        :: "r"(dst), "l"(src), "r"(bytes), "r"(m) : "memory");
}
static __device__ __forceinline__ void fence_async() {
    asm volatile("fence.proxy.async.shared::cta;" ::: "memory");
}
static __device__ __forceinline__ uint32_t mapa_u32(uint32_t addr, uint32_t rank) {
    uint32_t r;
    asm("mapa.shared::cluster.u32 %0, %1, %2;" : "=r"(r) : "r"(addr), "r"(rank));
    return r;
}
static __device__ __forceinline__ void st_cluster_v4(uint32_t addr, float a, float b,
                                                     float c, float d) {
    asm volatile("st.shared::cluster.v4.b32 [%0], {%1, %2, %3, %4};"
                 :: "r"(addr), "f"(a), "f"(b), "f"(c), "f"(d) : "memory");
}
#define CLUSTER_ARRIVE() asm volatile("barrier.cluster.arrive.aligned;" ::: "memory")
#define CLUSTER_WAIT()   asm volatile("barrier.cluster.wait.aligned;"   ::: "memory")

// packed fp32x2 ops
static __device__ __forceinline__ uint64_t pack2(float v) {
    uint64_t r;
    asm("mov.b64 %0, {%1, %1};" : "=l"(r) : "f"(v));
    return r;
}
static __device__ __forceinline__ void fma2(uint64_t& d, uint64_t a, uint64_t b) {
    asm("fma.rn.f32x2 %0, %1, %2, %0;" : "+l"(d) : "l"(a), "l"(b));
}
static __device__ __forceinline__ float f32x2_lo(uint64_t v) {
    return __uint_as_float((uint32_t)v);
}
static __device__ __forceinline__ float f32x2_hi(uint64_t v) {
    return __uint_as_float((uint32_t)(v >> 32));
}
static __device__ __forceinline__ float sigmoidf_(float x) {
    return __fdividef(1.0f, 1.0f + __expf(-x));
}
static __device__ __forceinline__ float tanhf_(float x) {
    float ax = fabsf(x);
    float t  = __expf(-2.0f * ax);
    float r  = __fdividef(1.0f - t, 1.0f + t);
    return x >= 0.0f ? r : -r;
}

// ---------------------------------------------------------------- Wh reorder
// g_Wh2[q][k][s*128+l] = Wh[k][s*256 + q*128 + l]
__global__ void __launch_bounds__(256) k_prep(const float* __restrict__ Wh) {
    const int q = blockIdx.y;
    const int e = blockIdx.x * 256 + threadIdx.x;    // 0..98303
    const int k = e / NCOL;
    const int rem = e - k * NCOL;
    const int s = rem >> 7, l = rem & 127;
    g_Wh2[q * WH2_HALF + e] = Wh[k * H3_ + s * 256 + q * 128 + l];
}

// ---------------------------------------------------------------- gx = x @ Wx + (bx + bh)
// Output per-half: g_gx2[q][m][ s*128 + (n&127) ], m = t*256+b.  bh folded in.
__global__ void __launch_bounds__(256) k_gx(const float* __restrict__ x,
                                            const float* __restrict__ Wx,
                                            const float* __restrict__ bx,
                                            const float* __restrict__ bh) {
    __shared__ float As[16 * 66];
    __shared__ float Bs[16 * 64];
    const int tid = threadIdx.x;
    const int tx = tid & 15, ty = tid >> 4;
    const int n0 = blockIdx.x * 64;
    const int m0 = blockIdx.y * 64;

    uint64_t acc2[2][4];
#pragma unroll
    for (int p = 0; p < 2; p++)
#pragma unroll
        for (int c = 0; c < 4; c++) acc2[p][c] = 0ULL;

    for (int k0 = 0; k0 < IN_; k0 += 16) {
#pragma unroll
        for (int i = 0; i < 4; i++) {
            int e  = tid + i * 256;
            int mm = e >> 4, kk = e & 15;
            int m  = m0 + mm;
            int tt = m >> 8, bb = m & 255;
            As[kk * 66 + mm] = x[bb * (T_ * IN_) + tt * IN_ + k0 + kk];
        }
#pragma unroll
        for (int i = 0; i < 4; i++) {
            int e  = tid + i * 256;
            int kk = e >> 6, nn = e & 63;
            Bs[kk * 64 + nn] = Wx[(k0 + kk) * H3_ + n0 + nn];
        }
        __syncthreads();
#pragma unroll
        for (int kk = 0; kk < 16; kk++) {
            uint64_t a01 = *(const uint64_t*)&As[kk * 66 + ty * 4];
            uint64_t a23 = *(const uint64_t*)&As[kk * 66 + ty * 4 + 2];
            float4 b4 = *(const float4*)&Bs[kk * 64 + tx * 4];
            uint64_t p0 = pack2(b4.x), p1 = pack2(b4.y);
            uint64_t p2 = pack2(b4.z), p3 = pack2(b4.w);
            fma2(acc2[0][0], a01, p0); fma2(acc2[0][1], a01, p1);
            fma2(acc2[0][2], a01, p2); fma2(acc2[0][3], a01, p3);
            fma2(acc2[1][0], a23, p0); fma2(acc2[1][1], a23, p1);
            fma2(acc2[1][2], a23, p2); fma2(acc2[1][3], a23, p3);
        }
        __syncthreads();
    }
    const int n = n0 + tx * 4;                 // global col; all 4 in same (s,q) block
    const int q = (n >> 7) & 1;
    const int c384 = (n >> 8) * 128 + (n & 127);
    float4 bxv = *(const float4*)&bx[n];
    float4 bhv = *(const float4*)&bh[n];
    bxv.x += bhv.x; bxv.y += bhv.y; bxv.z += bhv.z; bxv.w += bhv.w;
    float* dst = g_gx2 + (size_t)q * GX2_HALF + c384;
#pragma unroll
    for (int p = 0; p < 2; p++) {
        float4 lo4, hi4;
        lo4.x = f32x2_lo(acc2[p][0]) + bxv.x;  hi4.x = f32x2_hi(acc2[p][0]) + bxv.x;
        lo4.y = f32x2_lo(acc2[p][1]) + bxv.y;  hi4.y = f32x2_hi(acc2[p][1]) + bxv.y;
        lo4.z = f32x2_lo(acc2[p][2]) + bxv.z;  hi4.z = f32x2_hi(acc2[p][2]) + bxv.z;
        lo4.w = f32x2_lo(acc2[p][3]) + bxv.w;  hi4.w = f32x2_hi(acc2[p][3]) + bxv.w;
        *(float4*)(dst + (size_t)(m0 + ty * 4 + 2 * p)     * NCOL) = lo4;
        *(float4*)(dst + (size_t)(m0 + ty * 4 + 2 * p + 1) * NCOL) = hi4;
    }
}

// ---------------------------------------------------------------- persistent CRU recurrence
// 64 clusters of 2 CTAs (R7 skeleton). Cluster owns 12 rows; CTA q owns gate cols
// {j, j+256, j+512}, j in [128q,128q+128). h stored DUPLICATED ({h,h} pairs) so the
// BROADCAST A operand is 3x LDS.128 (pre-packed f32x2, 3 crossbar cyc); threads own
// COLUMN PAIRS so the per-thread B operand is 3x LDS.64 (6 cyc). Crossbar 36 = FMA 36
// per kk per SM: both pipes at the 9216 cyc/step floor. Own-column K-chunks first;
// split cluster arrive/wait hides the barrier + DSMEM h-exchange under 4 chunks.
__global__ void __launch_bounds__(PTH) __cluster_dims__(2, 1, 1)
k_cru(const float* __restrict__ h0) {
    extern __shared__ float sm[];
    float* hst0 = sm;                                   // [256][HSTR] h buffer 0 (dup'd)
    float* hst1 = sm + HST_FLOATS;                      // [256][HSTR] h buffer 1 (dup'd)
    float* Bs   = sm + 2 * HST_FLOATS;                  // [NBUF][KC][384] Wh chunks
    float* gxs  = sm + 2 * HST_FLOATS + BS_FLOATS;      // [12][384] gx tile
    uint64_t* mb = (uint64_t*)(sm + SMEM_FLOATS);       // 3 Wh + 1 gx barriers

    const int tid = threadIdx.x;
    const int wg  = tid >> 6;           // 0/1 -> rows 6wg..6wg+5
    const int u   = tid & 63;           // col pair 2u, 2u+1 per segment
    const int q   = blockIdx.x & 1;     // cluster rank
    const int q4  = 4 * q;              // first own chunk
    const int r0  = (blockIdx.x >> 1) * RWS;
    const int b_base = r0 & (B_ - 1);
    const int jh0 = q * 128 + 2 * u;    // first owned h column

    uint32_t mbw[NBUF], mbg;
#pragma unroll
    for (int i = 0; i < NBUF; i++) mbw[i] = s2u(mb + i);
    mbg = s2u(mb + NBUF);
    const uint32_t bsu  = s2u(Bs);
    const uint32_t gxsu = s2u(gxs);
    const uint32_t h0u  = s2u(hst0);
    const uint32_t h1u  = s2u(hst1);
    const uint32_t peer_h0 = mapa_u32(h0u, q ^ 1);
    const uint32_t peer_h1 = mapa_u32(h1u, q ^ 1);
    const float* whq = g_Wh2 + q * WH2_HALF;

    // initial h (duplicated): hst0[k*HSTR + 2r] = hst0[.. + 2r+1] = h0[(r0+r)*H + k]
    for (int idx = tid; idx < RWS * H_; idx += PTH) {
        const int r = idx >> 8, k = idx & 255;
        const float v = h0[(r0 + r) * H_ + k];
        hst0[k * HSTR + 2 * r]     = v;
        hst0[k * HSTR + 2 * r + 1] = v;
    }

    if (tid == 0) {
#pragma unroll
        for (int i = 0; i < NBUF; i++) mbar_init(mbw[i], 1);
        mbar_init(mbg, 1);
        fence_async();
    }
    __syncthreads();

    // prologue: 3 Wh chunks (own-first order) + gx(t=0)
    if (tid == 0) {
#pragma unroll
        for (int i = 0; i < NBUF; i++) {
            const int ch = (q4 + i) & (NCHUNK - 1);
            mbar_expect(mbw[i], CHUNK_BYTES);
            bulk_g2s(bsu + i * CHUNK_BYTES, whq + ch * (KC * NCOL), CHUNK_BYTES, mbw[i]);
        }
        const int n1 = (b_base + RWS > B_) ? (B_ - b_base) : RWS;
        mbar_expect(mbg, GX_BYTES);
        bulk_g2s(gxsu, g_gx2 + (size_t)q * GX2_HALF + (size_t)b_base * NCOL,
                 n1 * NCOL * 4, mbg);
        if (n1 < RWS)
            bulk_g2s(gxsu + n1 * NCOL * 4, g_gx2 + (size_t)q * GX2_HALF,
                     (RWS - n1) * NCOL * 4, mbg);
    }

    int phw[NBUF] = {0, 0, 0};
    int phg = 0;
    int cc = 0;
    const int CCMAX = NCHUNK * T_;

    CLUSTER_ARRIVE();   // pairs with the wait inside step 0's GEMM

    for (int t = 0; t < T_; t++) {
        const float* hcur = (t & 1) ? hst1 : hst0;
        float* hnxt = (t & 1) ? hst0 : hst1;
        const uint32_t hn_peer = (t & 1) ? peer_h0 : peer_h1;

        uint64_t acc[6][3];   // [row][segment], lanes = col pair
#pragma unroll
        for (int r = 0; r < 6; r++)
#pragma unroll
            for (int s = 0; s < 3; s++) acc[r][s] = 0ULL;

        for (int i = 0; i < NCHUNK; i++) {
            if (i == 4) CLUSTER_WAIT();   // peer h columns needed from here on

            const int buf = cc % NBUF;
            mbar_wait(mbw[buf], phw[buf]);
            phw[buf] ^= 1;

            const int ch = (q4 + i) & (NCHUNK - 1);
            const float* bp = Bs + buf * (KC * NCOL) + 2 * u;
            const float* hp = hcur + ch * (KC * HSTR) + 12 * wg;
#pragma unroll 8
            for (int kk = 0; kk < KC; kk++) {
                // A: 3x LDS.128 broadcast of duplicated row pairs
                ulonglong2 A0 = *(const ulonglong2*)(hp + kk * HSTR + 0);  // dup(r0),dup(r1)
                ulonglong2 A1 = *(const ulonglong2*)(hp + kk * HSTR + 4);  // dup(r2),dup(r3)
                ulonglong2 A2 = *(const ulonglong2*)(hp + kk * HSTR + 8);  // dup(r4),dup(r5)
                // B: 3x LDS.64 coalesced col pairs
                uint64_t b0 = *(const uint64_t*)(bp + kk * NCOL);
                uint64_t b1 = *(const uint64_t*)(bp + kk * NCOL + 128);
                uint64_t b2 = *(const uint64_t*)(bp + kk * NCOL + 256);
                fma2(acc[0][0], A0.x, b0); fma2(acc[0][1], A0.x, b1); fma2(acc[0][2], A0.x, b2);
                fma2(acc[1][0], A0.y, b0); fma2(acc[1][1], A0.y, b1); fma2(acc[1][2], A0.y, b2);
                fma2(acc[2][0], A1.x, b0); fma2(acc[2][1], A1.x, b1); fma2(acc[2][2], A1.x, b2);
                fma2(acc[3][0], A1.y, b0); fma2(acc[3][1], A1.y, b1); fma2(acc[3][2], A1.y, b2);
                fma2(acc[4][0], A2.x, b0); fma2(acc[4][1], A2.x, b1); fma2(acc[4][2], A2.x, b2);
                fma2(acc[5][0], A2.y, b0); fma2(acc[5][1], A2.y, b1); fma2(acc[5][2], A2.y, b2);
            }
            __syncthreads();   // buffer free for reuse
            if (tid == 0 && cc + NBUF < CCMAX) {
                const int nch = (q4 + ((cc + NBUF) & (NCHUNK - 1))) & (NCHUNK - 1);
                const uint32_t m = mbw[buf];
                mbar_expect(m, CHUNK_BYTES);
                bulk_g2s(bsu + buf * CHUNK_BYTES, whq + nch * (KC * NCOL), CHUNK_BYTES, m);
            }
            cc++;
        }

        // gate epilogue — per thread: 6 rows x 2 cols; stores dup'd h local + peer
        mbar_wait(mbg, phg); phg ^= 1;
        float nv[6][2];
#pragma unroll
        for (int r = 0; r < 6; r++) {
            const int R = 6 * wg + r;
            const uint64_t x0 = *(const uint64_t*)&gxs[R * NCOL + 2 * u];
            const uint64_t x1 = *(const uint64_t*)&gxs[R * NCOL + 128 + 2 * u];
            const uint64_t x2 = *(const uint64_t*)&gxs[R * NCOL + 256 + 2 * u];
#pragma unroll
            for (int c = 0; c < 2; c++) {
                const float hr = c ? f32x2_hi(acc[r][0]) : f32x2_lo(acc[r][0]);
                const float hz = c ? f32x2_hi(acc[r][1]) : f32x2_lo(acc[r][1]);
                const float hn = c ? f32x2_hi(acc[r][2]) : f32x2_lo(acc[r][2]);
                const float xr = c ? f32x2_hi(x0) : f32x2_lo(x0);
                const float xz = c ? f32x2_hi(x1) : f32x2_lo(x1);
                const float xn = c ? f32x2_hi(x2) : f32x2_lo(x2);
                const float rg = sigmoidf_(xr + hr);
                const float zg = sigmoidf_(xz + hz);
                const float ng = tanhf_(xn + rg * hn);
                const float ho = hcur[(jh0 + c) * HSTR + 2 * R];   // dup'd: lane 0
                nv[r][c] = ng + zg * (ho - ng);
            }
        }
        // store 3x v4 per col (rows duplicated), local + peer
#pragma unroll
        for (int c = 0; c < 2; c++) {
            const int colbase = (jh0 + c) * HSTR + 12 * wg;
#pragma unroll
            for (int p = 0; p < 3; p++) {
                const float v0 = nv[2 * p][c], v1 = nv[2 * p + 1][c];
                float4 d; d.x = v0; d.y = v0; d.z = v1; d.w = v1;
                *(float4*)(hnxt + colbase + 4 * p) = d;
                st_cluster_v4(hn_peer + (uint32_t)(colbase + 4 * p) * 4u, v0, v0, v1, v1);
            }
        }

        __syncthreads();   // local h writes visible; gxs fully consumed

        if (tid == 0 && t + 1 < T_) {
            const int n1 = (b_base + RWS > B_) ? (B_ - b_base) : RWS;
            mbar_expect(mbg, GX_BYTES);
            bulk_g2s(gxsu, g_gx2 + (size_t)q * GX2_HALF +
                     ((size_t)(t + 1) * B_ + b_base) * NCOL, n1 * NCOL * 4, mbg);
            if (n1 < RWS)
                bulk_g2s(gxsu + n1 * NCOL * 4,
                         g_gx2 + (size_t)q * GX2_HALF + (size_t)(t + 1) * B_ * NCOL,
                         (RWS - n1) * NCOL * 4, mbg);
        }

        CLUSTER_ARRIVE();   // releases peer h stores; consumed at next step's i==4
    }

    CLUSTER_WAIT();    // drain final phase; peer remote stores complete before exit

    // final h (T even -> hst0); each CTA stores its own column half
    for (int idx = tid; idx < RWS * 128; idx += PTH) {
        const int r = idx >> 7, l = idx & 127;
        g_hT[(r0 + r) * H_ + q * 128 + l] = hst0[(q * 128 + l) * HSTR + 2 * r];
    }
}

// ---------------------------------------------------------------- out = elu((sum_c hT) @ Wf + bf)
__global__ void __launch_bounds__(128) k_out(const float* __restrict__ Wf,
                                             const float* __restrict__ bf,
                                             float* __restrict__ out) {
    __shared__ float s[H_];
    const int b = blockIdx.x;
    const int tid = threadIdx.x;
    for (int k = tid; k < H_; k += 128)
        s[k] = g_hT[b * H_ + k] + g_hT[B_ * H_ + b * H_ + k] + g_hT[2 * B_ * H_ + b * H_ + k];
    __syncthreads();
    float acc = bf[tid];
#pragma unroll 8
    for (int k = 0; k < H_; k++)
        acc = fmaf(s[k], Wf[k * OUT_ + tid], acc);
    out[b * OUT_ + tid] = acc > 0.0f ? acc : expm1f(acc);
}

// ---------------------------------------------------------------- feature = mean_b hT -> (3, H)
__global__ void __launch_bounds__(256) k_feat(float* __restrict__ feat) {
    __shared__ float p[8][32];
    const int tx = threadIdx.x & 31, ty = threadIdx.x >> 5;
    const int jg = blockIdx.x * 32 + tx;            // 0..767
    const int c = jg >> 8, j = jg & 255;
    float s = 0.0f;
#pragma unroll 8
    for (int i = 0; i < 32; i++) {
        const int b = ty * 32 + i;
        s += g_hT[c * (B_ * H_) + b * H_ + j];
    }
    p[ty][tx] = s;
    __syncthreads();
    if (ty == 0) {
        float acc = 0.0f;
#pragma unroll
        for (int qq = 0; qq < 8; qq++) acc += p[qq][tx];
        feat[jg] = acc * (1.0f / 256.0f);
    }
}

// ---------------------------------------------------------------- launch
extern "C" void kernel_launch(void* const* d_in, const int* in_sizes, int n_in,
                              void* d_out, int out_size) {
    const float* x  = (const float*)d_in[0];
    const float* h0 = (const float*)d_in[1];
    const float* Wx = (const float*)d_in[2];
    const float* bx = (const float*)d_in[3];
    const float* Wh = (const float*)d_in[4];
    const float* bh = (const float*)d_in[5];
    const float* Wf = (const float*)d_in[6];
    const float* bf = (const float*)d_in[7];
    float* out = (float*)d_out;

    cudaFuncSetAttribute(k_cru, cudaFuncAttributeMaxDynamicSharedMemorySize, SMEM_BYTES);

    dim3 gp(WH2_HALF / 256, 2);          // (384, 2)
    k_prep<<<gp, 256>>>(Wh);
    dim3 g1(H3_ / 64, (T_ * B_) / 64);   // (12, 512)
    k_gx<<<g1, 256>>>(x, Wx, bx, bh);
    k_cru<<<NBLK, PTH, SMEM_BYTES>>>(h0);
    k_out<<<B_, 128>>>(Wf, bf, out);
    k_feat<<<24, 256>>>(out + (out_size - 3 * H_));
}

// round 11
// speedup vs baseline: 1.9640x; 1.0749x over previous
#include <cuda_runtime.h>
#include <cstdint>

#define B_   256
#define T_   128
#define IN_  128
#define H_   256
#define H3_  768
#define OUT_ 128

// ---- persistent recurrence: 64 clusters x 2 CTAs, 12 rows per cluster (R7 skeleton)
#define RWS  12                    // (c,b) state rows per cluster
#define NBLK 128                   // CTAs (64 clusters of 2)
#define PTH  256                   // 8 warps (2/SMSP); wg = tid>>7 -> rows 6wg..6wg+5; j = tid&127
#define NCOL 384                   // gate columns per CTA (3 segments of 128)
#define KC   32                    // k rows of Wh per chunk
#define NCHUNK (H_/KC)             // 8
#define NBUF 3
#define CHUNK_BYTES (KC*NCOL*4)    // 49152
#define GX_BYTES (RWS*NCOL*4)      // 18432
// h column layout (floats): rows 0-5 at [0..5], pad [6..7], rows 6-11 at [8..13], pad [14..19]
// -> per-wg A operand is one LDS.128 (rows 0-3) + one LDS.64 (rows 4-5), 16B-aligned.
#define HSTR 20
#define HST_FLOATS (H_*HSTR)       // 5120
#define BS_FLOATS  (NBUF*KC*NCOL)  // 36864
#define GXS_FLOATS (RWS*NCOL)      // 4608
#define SMEM_FLOATS (2*HST_FLOATS + BS_FLOATS + GXS_FLOATS)   // 51712
#define SMEM_BYTES  (SMEM_FLOATS*4 + 64)                      // 206912

#define WH2_HALF (H_*NCOL)             // 98304 floats per half
#define GX2_HALF ((size_t)T_*B_*NCOL)  // 12.58M floats per half

// scratch (device globals: allocation-free)
__device__ float g_Wh2[2 * WH2_HALF];            // [q][k][s*128+l] reordered Wh
__device__ float g_gx2[2 * GX2_HALF];            // [q][t*256+b][384] x@Wx+bx+bh, per-half cols
__device__ float g_hT[3 * B_ * H_];              // final hidden state

// ---------------------------------------------------------------- helpers
static __device__ __forceinline__ uint32_t s2u(const void* p) {
    uint32_t a;
    asm("{ .reg .u64 t; cvta.to.shared.u64 t, %1; cvt.u32.u64 %0, t; }"
        : "=r"(a) : "l"(p));
    return a;
}
static __device__ __forceinline__ void mbar_init(uint32_t m, int cnt) {
    asm volatile("mbarrier.init.shared.b64 [%0], %1;" :: "r"(m), "r"(cnt) : "memory");
}
static __device__ __forceinline__ void mbar_expect(uint32_t m, uint32_t bytes) {
    asm volatile("mbarrier.arrive.expect_tx.shared.b64 _, [%0], %1;"
                 :: "r"(m), "r"(bytes) : "memory");
}
static __device__ __forceinline__ void mbar_wait(uint32_t m, int ph) {
    asm volatile(
        "{\n\t"
        ".reg .pred P;\n\t"
        "WL%=:\n\t"
        "mbarrier.try_wait.parity.acquire.cta.shared::cta.b64 P, [%0], %1;\n\t"
        "@P bra WD%=;\n\t"
        "bra WL%=;\n\t"
        "WD%=:\n\t"
        "}"
        :: "r"(m), "r"(ph) : "memory");
}
static __device__ __forceinline__ void bulk_g2s(uint32_t dst, const void* src,
                                                uint32_t bytes, uint32_t m) {
    asm volatile(
        "cp.async.bulk.shared::cluster.global.mbarrier::complete_tx::bytes [%0], [%1], %2, [%3];"
        :: "r"(dst), "l"(src), "r"(bytes), "r"(m) : "memory");
}
static __device__ __forceinline__ void fence_async() {
    asm volatile("fence.proxy.async.shared::cta;" ::: "memory");
}
static __device__ __forceinline__ uint32_t mapa_u32(uint32_t addr, uint32_t rank) {
    uint32_t r;
    asm("mapa.shared::cluster.u32 %0, %1, %2;" : "=r"(r) : "r"(addr), "r"(rank));
    return r;
}
static __device__ __forceinline__ void st_cluster_b64(uint32_t addr, uint64_t v) {
    asm volatile("st.shared::cluster.b64 [%0], %1;" :: "r"(addr), "l"(v) : "memory");
}
#define CLUSTER_ARRIVE() asm volatile("barrier.cluster.arrive.aligned;" ::: "memory")
#define CLUSTER_WAIT()   asm volatile("barrier.cluster.wait.aligned;"   ::: "memory")

// packed fp32x2 ops
static __device__ __forceinline__ uint64_t pack2(float v) {
    uint64_t r;
    asm("mov.b64 %0, {%1, %1};" : "=l"(r) : "f"(v));
    return r;
}
static __device__ __forceinline__ uint64_t pack2f(float lo, float hi) {
    uint64_t r;
    asm("mov.b64 %0, {%1, %2};" : "=l"(r) : "f"(lo), "f"(hi));
    return r;
}
static __device__ __forceinline__ void fma2(uint64_t& d, uint64_t a, uint64_t b) {
    asm("fma.rn.f32x2 %0, %1, %2, %0;" : "+l"(d) : "l"(a), "l"(b));
}
static __device__ __forceinline__ float f32x2_lo(uint64_t v) {
    return __uint_as_float((uint32_t)v);
}
static __device__ __forceinline__ float f32x2_hi(uint64_t v) {
    return __uint_as_float((uint32_t)(v >> 32));
}
static __device__ __forceinline__ float sigmoidf_(float x) {
    return __fdividef(1.0f, 1.0f + __expf(-x));
}
static __device__ __forceinline__ float tanhf_(float x) {
    float ax = fabsf(x);
    float t  = __expf(-2.0f * ax);
    float r  = __fdividef(1.0f - t, 1.0f + t);
    return x >= 0.0f ? r : -r;
}
// storage float-offset of cluster row r within an h column (pads at 6,7 and 14..19)
static __device__ __forceinline__ int roff(int r) { return r + ((r >= 6) ? 2 : 0); }

// ---------------------------------------------------------------- Wh reorder
// g_Wh2[q][k][s*128+l] = Wh[k][s*256 + q*128 + l]
__global__ void __launch_bounds__(256) k_prep(const float* __restrict__ Wh) {
    const int q = blockIdx.y;
    const int e = blockIdx.x * 256 + threadIdx.x;    // 0..98303
    const int k = e / NCOL;
    const int rem = e - k * NCOL;
    const int s = rem >> 7, l = rem & 127;
    g_Wh2[q * WH2_HALF + e] = Wh[k * H3_ + s * 256 + q * 128 + l];
}

// ---------------------------------------------------------------- gx = x @ Wx + (bx + bh)
// Output per-half: g_gx2[q][m][ s*128 + (n&127) ], m = t*256+b.  bh folded in.
__global__ void __launch_bounds__(256) k_gx(const float* __restrict__ x,
                                            const float* __restrict__ Wx,
                                            const float* __restrict__ bx,
                                            const float* __restrict__ bh) {
    __shared__ float As[16 * 66];
    __shared__ float Bs[16 * 64];
    const int tid = threadIdx.x;
    const int tx = tid & 15, ty = tid >> 4;
    const int n0 = blockIdx.x * 64;
    const int m0 = blockIdx.y * 64;

    uint64_t acc2[2][4];
#pragma unroll
    for (int p = 0; p < 2; p++)
#pragma unroll
        for (int c = 0; c < 4; c++) acc2[p][c] = 0ULL;

    for (int k0 = 0; k0 < IN_; k0 += 16) {
#pragma unroll
        for (int i = 0; i < 4; i++) {
            int e  = tid + i * 256;
            int mm = e >> 4, kk = e & 15;
            int m  = m0 + mm;
            int tt = m >> 8, bb = m & 255;
            As[kk * 66 + mm] = x[bb * (T_ * IN_) + tt * IN_ + k0 + kk];
        }
#pragma unroll
        for (int i = 0; i < 4; i++) {
            int e  = tid + i * 256;
            int kk = e >> 6, nn = e & 63;
            Bs[kk * 64 + nn] = Wx[(k0 + kk) * H3_ + n0 + nn];
        }
        __syncthreads();
#pragma unroll
        for (int kk = 0; kk < 16; kk++) {
            uint64_t a01 = *(const uint64_t*)&As[kk * 66 + ty * 4];
            uint64_t a23 = *(const uint64_t*)&As[kk * 66 + ty * 4 + 2];
            float4 b4 = *(const float4*)&Bs[kk * 64 + tx * 4];
            uint64_t p0 = pack2(b4.x), p1 = pack2(b4.y);
            uint64_t p2 = pack2(b4.z), p3 = pack2(b4.w);
            fma2(acc2[0][0], a01, p0); fma2(acc2[0][1], a01, p1);
            fma2(acc2[0][2], a01, p2); fma2(acc2[0][3], a01, p3);
            fma2(acc2[1][0], a23, p0); fma2(acc2[1][1], a23, p1);
            fma2(acc2[1][2], a23, p2); fma2(acc2[1][3], a23, p3);
        }
        __syncthreads();
    }
    const int n = n0 + tx * 4;                 // global col; all 4 in same (s,q) block
    const int q = (n >> 7) & 1;
    const int c384 = (n >> 8) * 128 + (n & 127);
    float4 bxv = *(const float4*)&bx[n];
    float4 bhv = *(const float4*)&bh[n];
    bxv.x += bhv.x; bxv.y += bhv.y; bxv.z += bhv.z; bxv.w += bhv.w;
    float* dst = g_gx2 + (size_t)q * GX2_HALF + c384;
#pragma unroll
    for (int p = 0; p < 2; p++) {
        float4 lo4, hi4;
        lo4.x = f32x2_lo(acc2[p][0]) + bxv.x;  hi4.x = f32x2_hi(acc2[p][0]) + bxv.x;
        lo4.y = f32x2_lo(acc2[p][1]) + bxv.y;  hi4.y = f32x2_hi(acc2[p][1]) + bxv.y;
        lo4.z = f32x2_lo(acc2[p][2]) + bxv.z;  hi4.z = f32x2_hi(acc2[p][2]) + bxv.z;
        lo4.w = f32x2_lo(acc2[p][3]) + bxv.w;  hi4.w = f32x2_hi(acc2[p][3]) + bxv.w;
        *(float4*)(dst + (size_t)(m0 + ty * 4 + 2 * p)     * NCOL) = lo4;
        *(float4*)(dst + (size_t)(m0 + ty * 4 + 2 * p + 1) * NCOL) = hi4;
    }
}

// ---------------------------------------------------------------- persistent CRU recurrence
// 64 clusters of 2 CTAs (proven R7 structure). Cluster owns 12 rows; CTA q owns gate
// cols {j, j+256, j+512}, j in [128q,128q+128). h transposed in SMEM with row pairs
// packed and wg-halves 16B-aligned: per-wg A operand = LDS.128 + LDS.64 broadcast
// (2 crossbar transactions, was 3) -> crossbar 40 cyc/kk vs FMA 36. 8 warps (2/SMSP).
// Wh streamed from L2 (3-deep ring), own-column chunks first; split cluster
// arrive/wait hides barrier + DSMEM h-exchange under 4 chunks of GEMM.
__global__ void __launch_bounds__(PTH) __cluster_dims__(2, 1, 1)
k_cru(const float* __restrict__ h0) {
    extern __shared__ float sm[];
    float* hst0 = sm;                                   // [256][HSTR] h buffer 0
    float* hst1 = sm + HST_FLOATS;                      // [256][HSTR] h buffer 1
    float* Bs   = sm + 2 * HST_FLOATS;                  // [NBUF][KC][384] Wh chunks
    float* gxs  = sm + 2 * HST_FLOATS + BS_FLOATS;      // [12][384] gx tile
    uint64_t* mb = (uint64_t*)(sm + SMEM_FLOATS);       // 3 Wh + 1 gx barriers

    const int tid = threadIdx.x;
    const int wg  = tid >> 7;           // 0/1 -> rows 6wg..6wg+5
    const int j   = tid & 127;
    const int q   = blockIdx.x & 1;     // cluster rank
    const int q4  = 4 * q;              // first own chunk
    const int r0  = (blockIdx.x >> 1) * RWS;
    const int b_base = r0 & (B_ - 1);
    const int jh  = q * 128 + j;        // owned h column

    uint32_t mbw[NBUF], mbg;
#pragma unroll
    for (int i = 0; i < NBUF; i++) mbw[i] = s2u(mb + i);
    mbg = s2u(mb + NBUF);
    const uint32_t bsu  = s2u(Bs);
    const uint32_t gxsu = s2u(gxs);
    const uint32_t h0u  = s2u(hst0);
    const uint32_t h1u  = s2u(hst1);
    const uint32_t peer_h0 = mapa_u32(h0u, q ^ 1);
    const uint32_t peer_h1 = mapa_u32(h1u, q ^ 1);
    const float* whq = g_Wh2 + q * WH2_HALF;

    // initial h: h0[(r0+r)*H + k] -> hst0[k*HSTR + roff(r)]
    for (int idx = tid; idx < RWS * H_; idx += PTH) {
        const int r = idx >> 8, k = idx & 255;
        hst0[k * HSTR + roff(r)] = h0[(r0 + r) * H_ + k];
    }

    if (tid == 0) {
#pragma unroll
        for (int i = 0; i < NBUF; i++) mbar_init(mbw[i], 1);
        mbar_init(mbg, 1);
        fence_async();
    }
    __syncthreads();

    // prologue: 3 Wh chunks (own-first order) + gx(t=0)
    if (tid == 0) {
#pragma unroll
        for (int i = 0; i < NBUF; i++) {
            const int ch = (q4 + i) & (NCHUNK - 1);
            mbar_expect(mbw[i], CHUNK_BYTES);
            bulk_g2s(bsu + i * CHUNK_BYTES, whq + ch * (KC * NCOL), CHUNK_BYTES, mbw[i]);
        }
        const int n1 = (b_base + RWS > B_) ? (B_ - b_base) : RWS;
        mbar_expect(mbg, GX_BYTES);
        bulk_g2s(gxsu, g_gx2 + (size_t)q * GX2_HALF + (size_t)b_base * NCOL,
                 n1 * NCOL * 4, mbg);
        if (n1 < RWS)
            bulk_g2s(gxsu + n1 * NCOL * 4, g_gx2 + (size_t)q * GX2_HALF,
                     (RWS - n1) * NCOL * 4, mbg);
    }

    int phw[NBUF] = {0, 0, 0};
    int phg = 0;
    int cc = 0;
    const int CCMAX = NCHUNK * T_;

    CLUSTER_ARRIVE();   // pairs with the wait inside step 0's GEMM

    for (int t = 0; t < T_; t++) {
        const float* hcur = (t & 1) ? hst1 : hst0;
        float* hnxt = (t & 1) ? hst0 : hst1;
        const uint32_t hn_peer = (t & 1) ? peer_h0 : peer_h1;

        uint64_t acc[3][3];   // [row-pair][segment], lanes = row pair
#pragma unroll
        for (int p = 0; p < 3; p++)
#pragma unroll
            for (int s = 0; s < 3; s++) acc[p][s] = 0ULL;

        for (int i = 0; i < NCHUNK; i++) {
            if (i == 4) CLUSTER_WAIT();   // peer h columns needed from here on

            const int buf = cc % NBUF;
            mbar_wait(mbw[buf], phw[buf]);
            phw[buf] ^= 1;

            const int ch = (q4 + i) & (NCHUNK - 1);
            const float* bp = Bs + buf * (KC * NCOL) + j;
            const float* hp = hcur + ch * (KC * HSTR) + 8 * wg;
#pragma unroll
            for (int kk = 0; kk < KC; kk++) {
                // A: LDS.128 (rows 0-3 of this wg, packed pairs) + LDS.64 (rows 4-5)
                ulonglong2 A0 = *(const ulonglong2*)(hp + kk * HSTR);
                uint64_t   a2 = *(const uint64_t*)(hp + kk * HSTR + 4);
                // B: 3x scalar LDS.32 + pack2 (one per segment)
                uint64_t p0 = pack2(bp[kk * NCOL]);
                uint64_t p1 = pack2(bp[kk * NCOL + 128]);
                uint64_t p2 = pack2(bp[kk * NCOL + 256]);
                fma2(acc[0][0], A0.x, p0); fma2(acc[0][1], A0.x, p1); fma2(acc[0][2], A0.x, p2);
                fma2(acc[1][0], A0.y, p0); fma2(acc[1][1], A0.y, p1); fma2(acc[1][2], A0.y, p2);
                fma2(acc[2][0], a2,   p0); fma2(acc[2][1], a2,   p1); fma2(acc[2][2], a2,   p2);
            }
            __syncthreads();   // buffer free for reuse
            if (tid == 0 && cc + NBUF < CCMAX) {
                const int nch = (q4 + ((cc + NBUF) & (NCHUNK - 1))) & (NCHUNK - 1);
                const uint32_t m = mbw[buf];
                mbar_expect(m, CHUNK_BYTES);
                bulk_g2s(bsu + buf * CHUNK_BYTES, whq + nch * (KC * NCOL), CHUNK_BYTES, m);
            }
            cc++;
        }

        // gate epilogue — register-resident; write h(next) locally and to peer
        mbar_wait(mbg, phg); phg ^= 1;
#pragma unroll
        for (int p = 0; p < 3; p++) {
            float nv[2];
#pragma unroll
            for (int hi = 0; hi < 2; hi++) {
                const int R = 6 * wg + 2 * p + hi;     // cluster row
                const float hr = hi ? f32x2_hi(acc[p][0]) : f32x2_lo(acc[p][0]);
                const float hz = hi ? f32x2_hi(acc[p][1]) : f32x2_lo(acc[p][1]);
                const float hn = hi ? f32x2_hi(acc[p][2]) : f32x2_lo(acc[p][2]);
                const float xr = gxs[R * NCOL + j];
                const float xz = gxs[R * NCOL + 128 + j];
                const float xn = gxs[R * NCOL + 256 + j];
                const float rg = sigmoidf_(xr + hr);
                const float zg = sigmoidf_(xz + hz);
                const float ng = tanhf_(xn + rg * hn);
                const float ho = hcur[jh * HSTR + 8 * wg + 2 * p + hi];
                nv[hi] = ng + zg * (ho - ng);
            }
            const uint64_t pr = pack2f(nv[0], nv[1]);
            const uint32_t off = (uint32_t)(jh * HSTR + 8 * wg + 2 * p) * 4u;
            *(uint64_t*)((char*)sm + (((t & 1) ? h0u : h1u) - s2u(sm)) + off) = pr; // local
            st_cluster_b64(hn_peer + off, pr);                                      // peer
            (void)hnxt;
        }

        __syncthreads();   // local h writes visible; gxs fully consumed

        if (tid == 0 && t + 1 < T_) {
            const int n1 = (b_base + RWS > B_) ? (B_ - b_base) : RWS;
            mbar_expect(mbg, GX_BYTES);
            bulk_g2s(gxsu, g_gx2 + (size_t)q * GX2_HALF +
                     ((size_t)(t + 1) * B_ + b_base) * NCOL, n1 * NCOL * 4, mbg);
            if (n1 < RWS)
                bulk_g2s(gxsu + n1 * NCOL * 4,
                         g_gx2 + (size_t)q * GX2_HALF + (size_t)(t + 1) * B_ * NCOL,
                         (RWS - n1) * NCOL * 4, mbg);
        }

        CLUSTER_ARRIVE();   // releases peer h stores; consumed at next step's i==4
    }

    CLUSTER_WAIT();    // drain final phase; peer remote stores complete before exit

    // final h (T even -> hst0); each CTA stores its own column half
    for (int idx = tid; idx < RWS * 128; idx += PTH) {
        const int r = idx >> 7, l = idx & 127;
        g_hT[(r0 + r) * H_ + q * 128 + l] = hst0[(q * 128 + l) * HSTR + roff(r)];
    }
}

// ---------------------------------------------------------------- out = elu((sum_c hT) @ Wf + bf)
__global__ void __launch_bounds__(128) k_out(const float* __restrict__ Wf,
                                             const float* __restrict__ bf,
                                             float* __restrict__ out) {
    __shared__ float s[H_];
    const int b = blockIdx.x;
    const int tid = threadIdx.x;
    for (int k = tid; k < H_; k += 128)
        s[k] = g_hT[b * H_ + k] + g_hT[B_ * H_ + b * H_ + k] + g_hT[2 * B_ * H_ + b * H_ + k];
    __syncthreads();
    float acc = bf[tid];
#pragma unroll 8
    for (int k = 0; k < H_; k++)
        acc = fmaf(s[k], Wf[k * OUT_ + tid], acc);
    out[b * OUT_ + tid] = acc > 0.0f ? acc : expm1f(acc);
}

// ---------------------------------------------------------------- feature = mean_b hT -> (3, H)
__global__ void __launch_bounds__(256) k_feat(float* __restrict__ feat) {
    __shared__ float p[8][32];
    const int tx = threadIdx.x & 31, ty = threadIdx.x >> 5;
    const int jg = blockIdx.x * 32 + tx;            // 0..767
    const int c = jg >> 8, j = jg & 255;
    float s = 0.0f;
#pragma unroll 8
    for (int i = 0; i < 32; i++) {
        const int b = ty * 32 + i;
        s += g_hT[c * (B_ * H_) + b * H_ + j];
    }
    p[ty][tx] = s;
    __syncthreads();
    if (ty == 0) {
        float acc = 0.0f;
#pragma unroll
        for (int qq = 0; qq < 8; qq++) acc += p[qq][tx];
        feat[jg] = acc * (1.0f / 256.0f);
    }
}

// ---------------------------------------------------------------- launch
extern "C" void kernel_launch(void* const* d_in, const int* in_sizes, int n_in,
                              void* d_out, int out_size) {
    const float* x  = (const float*)d_in[0];
    const float* h0 = (const float*)d_in[1];
    const float* Wx = (const float*)d_in[2];
    const float* bx = (const float*)d_in[3];
    const float* Wh = (const float*)d_in[4];
    const float* bh = (const float*)d_in[5];
    const float* Wf = (const float*)d_in[6];
    const float* bf = (const float*)d_in[7];
    float* out = (float*)d_out;

    cudaFuncSetAttribute(k_cru, cudaFuncAttributeMaxDynamicSharedMemorySize, SMEM_BYTES);

    dim3 gp(WH2_HALF / 256, 2);          // (384, 2)
    k_prep<<<gp, 256>>>(Wh);
    dim3 g1(H3_ / 64, (T_ * B_) / 64);   // (12, 512)
    k_gx<<<g1, 256>>>(x, Wx, bx, bh);
    k_cru<<<NBLK, PTH, SMEM_BYTES>>>(h0);
    k_out<<<B_, 128>>>(Wf, bf, out);
    k_feat<<<24, 256>>>(out + (out_size - 3 * H_));
}

// round 12
// speedup vs baseline: 2.0677x; 1.0528x over previous
#include <cuda_runtime.h>
#include <cstdint>

#define B_   256
#define T_   128
#define IN_  128
#define H_   256
#define H3_  768
#define OUT_ 128

// ---- persistent recurrence: 64 clusters x 2 CTAs, 12 rows per cluster (R7 skeleton)
#define RWS  12                    // (c,b) state rows per cluster
#define NBLK 128                   // CTAs (64 clusters of 2)
#define PTH  256                   // 8 warps; wgid = tid>>7 -> k-split half; j = tid&127
#define NCOL 384                   // gate columns per CTA (3 segments of 128)
#define KC   32                    // k rows of Wh per chunk
#define NCHUNK (H_/KC)             // 8
#define NBUF 3
#define NSTREAM (NCHUNK*T_)        // 1024 chunk-streams
#define CHUNK_BYTES (KC*NCOL*4)    // 49152
#define GX_BYTES (RWS*NCOL*4)      // 18432
#define HSTR 14                    // h column stride (12 rows + 2 pad), row r at offset r
#define HST_FLOATS (H_*HSTR)       // 3584
#define BS_FLOATS  (NBUF*KC*NCOL)  // 36864
#define GXS_FLOATS (RWS*NCOL)      // 4608
#define XCH_FLOATS (9*2*128*2)     // 4608 (9 idx x 2 wg x 128 j, uint64 each)
#define SMEM_FLOATS (2*HST_FLOATS + BS_FLOATS + GXS_FLOATS + XCH_FLOATS)  // 53248
#define SMEM_BYTES  (SMEM_FLOATS*4 + 64)                                  // 213056

#define WH2_HALF (H_*NCOL)             // 98304 floats per half
#define GX2_HALF ((size_t)T_*B_*NCOL)  // 12.58M floats per half

// scratch (device globals: allocation-free)
__device__ float g_Wh2[2 * WH2_HALF];            // [q][k][s*128+l] reordered Wh
__device__ float g_gx2[2 * GX2_HALF];            // [q][t*256+b][384] x@Wx+bx, per-half cols
__device__ float g_hT[3 * B_ * H_];              // final hidden state

// ---------------------------------------------------------------- helpers
static __device__ __forceinline__ uint32_t s2u(const void* p) {
    uint32_t a;
    asm("{ .reg .u64 t; cvta.to.shared.u64 t, %1; cvt.u32.u64 %0, t; }"
        : "=r"(a) : "l"(p));
    return a;
}
static __device__ __forceinline__ void mbar_init(uint32_t m, int cnt) {
    asm volatile("mbarrier.init.shared.b64 [%0], %1;" :: "r"(m), "r"(cnt) : "memory");
}
static __device__ __forceinline__ void mbar_expect(uint32_t m, uint32_t bytes) {
    asm volatile("mbarrier.arrive.expect_tx.shared.b64 _, [%0], %1;"
                 :: "r"(m), "r"(bytes) : "memory");
}
static __device__ __forceinline__ void mbar_wait(uint32_t m, int ph) {
    asm volatile(
        "{\n\t"
        ".reg .pred P;\n\t"
        "WL%=:\n\t"
        "mbarrier.try_wait.parity.acquire.cta.shared::cta.b64 P, [%0], %1;\n\t"
        "@P bra WD%=;\n\t"
        "bra WL%=;\n\t"
        "WD%=:\n\t"
        "}"
        :: "r"(m), "r"(ph) : "memory");
}
static __device__ __forceinline__ void bulk_g2s(uint32_t dst, const void* src,
                                                uint32_t bytes, uint32_t m) {
    asm volatile(
        "cp.async.bulk.shared::cluster.global.mbarrier::complete_tx::bytes [%0], [%1], %2, [%3];"
        :: "r"(dst), "l"(src), "r"(bytes), "r"(m) : "memory");
}
static __device__ __forceinline__ void fence_async() {
    asm volatile("fence.proxy.async.shared::cta;" ::: "memory");
}
static __device__ __forceinline__ uint32_t mapa_u32(uint32_t addr, uint32_t rank) {
    uint32_t r;
    asm("mapa.shared::cluster.u32 %0, %1, %2;" : "=r"(r) : "r"(addr), "r"(rank));
    return r;
}
static __device__ __forceinline__ void st_cluster_b64(uint32_t addr, uint64_t v) {
    asm volatile("st.shared::cluster.b64 [%0], %1;" :: "r"(addr), "l"(v) : "memory");
}
static __device__ __forceinline__ void wg_bar(int id) {
    asm volatile("bar.sync %0, 128;" :: "r"(id) : "memory");
}
#define CLUSTER_ARRIVE() asm volatile("barrier.cluster.arrive.aligned;" ::: "memory")
#define CLUSTER_WAIT()   asm volatile("barrier.cluster.wait.aligned;"   ::: "memory")

// packed fp32x2 ops
static __device__ __forceinline__ uint64_t pack2(float v) {
    uint64_t r;
    asm("mov.b64 %0, {%1, %1};" : "=l"(r) : "f"(v));
    return r;
}
static __device__ __forceinline__ uint64_t pack2f(float lo, float hi) {
    uint64_t r;
    asm("mov.b64 %0, {%1, %2};" : "=l"(r) : "f"(lo), "f"(hi));
    return r;
}
static __device__ __forceinline__ void fma2(uint64_t& d, uint64_t a, uint64_t b) {
    asm("fma.rn.f32x2 %0, %1, %2, %0;" : "+l"(d) : "l"(a), "l"(b));
}
static __device__ __forceinline__ uint64_t addf2(uint64_t a, uint64_t b) {
    uint64_t o;
    asm("add.rn.f32x2 %0, %1, %2;" : "=l"(o) : "l"(a), "l"(b));
    return o;
}
static __device__ __forceinline__ float f32x2_lo(uint64_t v) {
    return __uint_as_float((uint32_t)v);
}
static __device__ __forceinline__ float f32x2_hi(uint64_t v) {
    return __uint_as_float((uint32_t)(v >> 32));
}
static __device__ __forceinline__ float sigmoidf_(float x) {
    return __fdividef(1.0f, 1.0f + __expf(-x));
}
static __device__ __forceinline__ float tanhf_(float x) {
    float ax = fabsf(x);
    float t  = __expf(-2.0f * ax);
    float r  = __fdividef(1.0f - t, 1.0f + t);
    return x >= 0.0f ? r : -r;
}

// ---------------------------------------------------------------- Wh reorder
// g_Wh2[q][k][s*128+l] = Wh[k][s*256 + q*128 + l]
__global__ void __launch_bounds__(256) k_prep(const float* __restrict__ Wh) {
    const int q = blockIdx.y;
    const int e = blockIdx.x * 256 + threadIdx.x;    // 0..98303
    const int k = e / NCOL;
    const int rem = e - k * NCOL;
    const int s = rem >> 7, l = rem & 127;
    g_Wh2[q * WH2_HALF + e] = Wh[k * H3_ + s * 256 + q * 128 + l];
}

// ---------------------------------------------------------------- gx = x @ Wx + bx  (FFMA2)
// Output per-half: g_gx2[q][m][ s*128 + (n&127) ], m = t*256+b.
__global__ void __launch_bounds__(256) k_gx(const float* __restrict__ x,
                                            const float* __restrict__ Wx,
                                            const float* __restrict__ bx) {
    __shared__ float As[16 * 66];
    __shared__ float Bs[16 * 64];
    const int tid = threadIdx.x;
    const int tx = tid & 15, ty = tid >> 4;
    const int n0 = blockIdx.x * 64;
    const int m0 = blockIdx.y * 64;

    uint64_t acc2[2][4];
#pragma unroll
    for (int p = 0; p < 2; p++)
#pragma unroll
        for (int c = 0; c < 4; c++) acc2[p][c] = 0ULL;

    for (int k0 = 0; k0 < IN_; k0 += 16) {
#pragma unroll
        for (int i = 0; i < 4; i++) {
            int e  = tid + i * 256;
            int mm = e >> 4, kk = e & 15;
            int m  = m0 + mm;
            int tt = m >> 8, bb = m & 255;
            As[kk * 66 + mm] = x[bb * (T_ * IN_) + tt * IN_ + k0 + kk];
        }
#pragma unroll
        for (int i = 0; i < 4; i++) {
            int e  = tid + i * 256;
            int kk = e >> 6, nn = e & 63;
            Bs[kk * 64 + nn] = Wx[(k0 + kk) * H3_ + n0 + nn];
        }
        __syncthreads();
#pragma unroll
        for (int kk = 0; kk < 16; kk++) {
            uint64_t a01 = *(const uint64_t*)&As[kk * 66 + ty * 4];
            uint64_t a23 = *(const uint64_t*)&As[kk * 66 + ty * 4 + 2];
            float4 b4 = *(const float4*)&Bs[kk * 64 + tx * 4];
            uint64_t p0 = pack2(b4.x), p1 = pack2(b4.y);
            uint64_t p2 = pack2(b4.z), p3 = pack2(b4.w);
            fma2(acc2[0][0], a01, p0); fma2(acc2[0][1], a01, p1);
            fma2(acc2[0][2], a01, p2); fma2(acc2[0][3], a01, p3);
            fma2(acc2[1][0], a23, p0); fma2(acc2[1][1], a23, p1);
            fma2(acc2[1][2], a23, p2); fma2(acc2[1][3], a23, p3);
        }
        __syncthreads();
    }
    const int n = n0 + tx * 4;                 // global col; all 4 in same (s,q) block
    const int q = (n >> 7) & 1;
    const int c384 = (n >> 8) * 128 + (n & 127);
    float4 bxv = *(const float4*)&bx[n];
    float* dst = g_gx2 + (size_t)q * GX2_HALF + c384;
#pragma unroll
    for (int p = 0; p < 2; p++) {
        float4 lo4, hi4;
        lo4.x = f32x2_lo(acc2[p][0]) + bxv.x;  hi4.x = f32x2_hi(acc2[p][0]) + bxv.x;
        lo4.y = f32x2_lo(acc2[p][1]) + bxv.y;  hi4.y = f32x2_hi(acc2[p][1]) + bxv.y;
        lo4.z = f32x2_lo(acc2[p][2]) + bxv.z;  hi4.z = f32x2_hi(acc2[p][2]) + bxv.z;
        lo4.w = f32x2_lo(acc2[p][3]) + bxv.w;  hi4.w = f32x2_hi(acc2[p][3]) + bxv.w;
        *(float4*)(dst + (size_t)(m0 + ty * 4 + 2 * p)     * NCOL) = lo4;
        *(float4*)(dst + (size_t)(m0 + ty * 4 + 2 * p + 1) * NCOL) = hi4;
    }
}

// ---------------------------------------------------------------- persistent CRU recurrence
// 64 clusters of 2 CTAs (R7 skeleton). Cluster owns 12 rows; CTA q owns gate cols
// {j, j+256, j+512}, j in [128q,128q+128). K-SPLIT across warp-groups: wg0 consumes
// even chunk-streams, wg1 odd — each accumulates partial gh for ALL 12 rows over its
// half of k. Per-step crossbar: A 6144 + B 3072 = 9216 = FMA floor (B duplication
// halved vs R7). Per-wg named barriers replace per-chunk __syncthreads; one SMEM
// exchange-reduce per step, then R7's epilogue (wg0 gates rows 0-5, wg1 rows 6-11).
// Own-column chunks first per wg; split cluster arrive/wait hides h exchange.
__global__ void __launch_bounds__(PTH) __cluster_dims__(2, 1, 1)
k_cru(const float* __restrict__ h0, const float* __restrict__ bh) {
    extern __shared__ float sm[];
    float* hst0 = sm;                                   // [256][HSTR] h buffer 0
    float* hst1 = sm + HST_FLOATS;                      // [256][HSTR] h buffer 1
    float* Bs   = sm + 2 * HST_FLOATS;                  // [NBUF][KC][384] Wh chunks
    float* gxs  = sm + 2 * HST_FLOATS + BS_FLOATS;      // [12][384] gx tile
    uint64_t* xch = (uint64_t*)(gxs + GXS_FLOATS);      // [9][2][128] partial exchange
    uint64_t* mb = (uint64_t*)(sm + SMEM_FLOATS);       // 3 Wh + 1 gx barriers

    const int tid  = threadIdx.x;
    const int wgid = tid >> 7;          // k-split half (0: even streams, 1: odd)
    const int j    = tid & 127;
    const int q    = blockIdx.x & 1;    // cluster rank
    const int q4   = 4 * q;             // first own chunk
    const int r0   = (blockIdx.x >> 1) * RWS;
    const int b_base = r0 & (B_ - 1);
    const int jh   = q * 128 + j;       // owned h column

    uint32_t mbw[NBUF], mbg;
#pragma unroll
    for (int i = 0; i < NBUF; i++) mbw[i] = s2u(mb + i);
    mbg = s2u(mb + NBUF);
    const uint32_t bsu  = s2u(Bs);
    const uint32_t gxsu = s2u(gxs);
    const uint32_t h0u  = s2u(hst0);
    const uint32_t h1u  = s2u(hst1);
    const uint32_t peer_h0 = mapa_u32(h0u, q ^ 1);
    const uint32_t peer_h1 = mapa_u32(h1u, q ^ 1);
    const float* whq = g_Wh2 + q * WH2_HALF;

    // initial h: h0[(r0+r)*H + k] -> hst0[k*HSTR + r]
    for (int idx = tid; idx < RWS * H_; idx += PTH) {
        const int r = idx >> 8, k = idx & 255;
        hst0[k * HSTR + r] = h0[(r0 + r) * H_ + k];
    }

    // bh for owned column (correct handling: bh lives in gh, inside r*hn)
    uint64_t bh2[3];
#pragma unroll
    for (int s = 0; s < 3; s++) bh2[s] = pack2(bh[s * H_ + jh]);

    if (tid == 0) {
#pragma unroll
        for (int i = 0; i < NBUF; i++) mbar_init(mbw[i], 1);
        mbar_init(mbg, 1);
        fence_async();
    }
    __syncthreads();

    // prologue: first 3 chunk-streams + gx(t=0)
    if (tid == 0) {
#pragma unroll
        for (int i = 0; i < NBUF; i++) {
            const int ch = (q4 + i) & (NCHUNK - 1);
            mbar_expect(mbw[i], CHUNK_BYTES);
            bulk_g2s(bsu + i * CHUNK_BYTES, whq + ch * (KC * NCOL), CHUNK_BYTES, mbw[i]);
        }
        const int n1 = (b_base + RWS > B_) ? (B_ - b_base) : RWS;
        mbar_expect(mbg, GX_BYTES);
        bulk_g2s(gxsu, g_gx2 + (size_t)q * GX2_HALF + (size_t)b_base * NCOL,
                 n1 * NCOL * 4, mbg);
        if (n1 < RWS)
            bulk_g2s(gxsu + n1 * NCOL * 4, g_gx2 + (size_t)q * GX2_HALF,
                     (RWS - n1) * NCOL * 4, mbg);
    }

    int phg = 0;
    const int give = wgid ? 0 : 3;      // row pairs handed to the other wg
    const int keep = wgid ? 3 : 0;      // row pairs this wg finalizes

    CLUSTER_ARRIVE();   // pairs with the waits inside step 0's GEMM

    for (int t = 0; t < T_; t++) {
        const float* hcur = (t & 1) ? hst1 : hst0;
        float* hnxt = (t & 1) ? hst0 : hst1;
        const uint32_t hn_peer = (t & 1) ? peer_h0 : peer_h1;

        // partial gh over this wg's k-half: bh2/2 per half would be wrong — init wg0
        // with bh2, wg1 with 0 (sum after exchange carries bh once).
        uint64_t acc[6][3];
#pragma unroll
        for (int p = 0; p < 6; p++)
#pragma unroll
            for (int s = 0; s < 3; s++) acc[p][s] = wgid ? 0ULL : bh2[s];

        // 4 chunk-streams per wg: s = t*8 + 2*il + wgid; chunk = (q4 + s%8) & 7
        for (int il = 0; il < 4; il++) {
            const int s = t * 8 + 2 * il + wgid;
            if (il == 2) CLUSTER_WAIT();        // peer h columns needed from here on

            const int buf = s % 3;
            mbar_wait(mbw[buf], (s / 3) & 1);

            const int ch = (q4 + (s & 7)) & (NCHUNK - 1);
            const float* bp = Bs + buf * (KC * NCOL) + j;
            const float* hp = hcur + ch * (KC * HSTR);
#pragma unroll 8
            for (int kk = 0; kk < KC; kk++) {
                uint64_t a0 = *(const uint64_t*)(hp + kk * HSTR + 0);
                uint64_t a1 = *(const uint64_t*)(hp + kk * HSTR + 2);
                uint64_t a2 = *(const uint64_t*)(hp + kk * HSTR + 4);
                uint64_t a3 = *(const uint64_t*)(hp + kk * HSTR + 6);
                uint64_t a4 = *(const uint64_t*)(hp + kk * HSTR + 8);
                uint64_t a5 = *(const uint64_t*)(hp + kk * HSTR + 10);
                uint64_t p0 = pack2(bp[kk * NCOL]);
                uint64_t p1 = pack2(bp[kk * NCOL + 128]);
                uint64_t p2 = pack2(bp[kk * NCOL + 256]);
                fma2(acc[0][0], a0, p0); fma2(acc[0][1], a0, p1); fma2(acc[0][2], a0, p2);
                fma2(acc[1][0], a1, p0); fma2(acc[1][1], a1, p1); fma2(acc[1][2], a1, p2);
                fma2(acc[2][0], a2, p0); fma2(acc[2][1], a2, p1); fma2(acc[2][2], a2, p2);
                fma2(acc[3][0], a3, p0); fma2(acc[3][1], a3, p1); fma2(acc[3][2], a3, p2);
                fma2(acc[4][0], a4, p0); fma2(acc[4][1], a4, p1); fma2(acc[4][2], a4, p2);
                fma2(acc[5][0], a5, p0); fma2(acc[5][1], a5, p1); fma2(acc[5][2], a5, p2);
            }
            wg_bar(1 + wgid);                   // this wg done with buf
            if ((tid & 127) == 0 && s + 3 < NSTREAM) {
                const int ns = s + 3;
                const int nb = ns % 3;
                const int nch = (q4 + (ns & 7)) & (NCHUNK - 1);
                mbar_expect(mbw[nb], CHUNK_BYTES);
                bulk_g2s(bsu + nb * CHUNK_BYTES, whq + nch * (KC * NCOL),
                         CHUNK_BYTES, mbw[nb]);
            }
        }

        // ---- exchange-reduce partials between wgs
        __syncthreads();
#pragma unroll
        for (int p = 0; p < 3; p++)
#pragma unroll
            for (int s = 0; s < 3; s++)
                xch[((p * 3 + s) * 2 + wgid) * 128 + j] = acc[give + p][s];
        __syncthreads();
#pragma unroll
        for (int p = 0; p < 3; p++)
#pragma unroll
            for (int s = 0; s < 3; s++)
                acc[keep + p][s] = addf2(acc[keep + p][s],
                                         xch[((p * 3 + s) * 2 + (wgid ^ 1)) * 128 + j]);

        // ---- gate epilogue: rows 6*wgid .. 6*wgid+5, col jh
        mbar_wait(mbg, phg); phg ^= 1;
#pragma unroll
        for (int pl = 0; pl < 3; pl++) {
            const int P = keep + pl;
            float nv[2];
#pragma unroll
            for (int hi = 0; hi < 2; hi++) {
                const int R = 6 * wgid + 2 * pl + hi;   // cluster row
                const float hr = hi ? f32x2_hi(acc[P][0]) : f32x2_lo(acc[P][0]);
                const float hz = hi ? f32x2_hi(acc[P][1]) : f32x2_lo(acc[P][1]);
                const float hn = hi ? f32x2_hi(acc[P][2]) : f32x2_lo(acc[P][2]);
                const float xr = gxs[R * NCOL + j];
                const float xz = gxs[R * NCOL + 128 + j];
                const float xn = gxs[R * NCOL + 256 + j];
                const float rg = sigmoidf_(xr + hr);
                const float zg = sigmoidf_(xz + hz);
                const float ng = tanhf_(xn + rg * hn);
                const float ho = hcur[jh * HSTR + R];
                nv[hi] = ng + zg * (ho - ng);
            }
            const uint64_t pr = pack2f(nv[0], nv[1]);
            const int off = jh * HSTR + 6 * wgid + 2 * pl;
            *(uint64_t*)(hnxt + off) = pr;                       // local
            st_cluster_b64(hn_peer + (uint32_t)off * 4u, pr);    // peer
        }

        __syncthreads();   // local h writes visible; gxs + xch fully consumed

        if (tid == 0 && t + 1 < T_) {
            const int n1 = (b_base + RWS > B_) ? (B_ - b_base) : RWS;
            mbar_expect(mbg, GX_BYTES);
            bulk_g2s(gxsu, g_gx2 + (size_t)q * GX2_HALF +
                     ((size_t)(t + 1) * B_ + b_base) * NCOL, n1 * NCOL * 4, mbg);
            if (n1 < RWS)
                bulk_g2s(gxsu + n1 * NCOL * 4,
                         g_gx2 + (size_t)q * GX2_HALF + (size_t)(t + 1) * B_ * NCOL,
                         (RWS - n1) * NCOL * 4, mbg);
        }

        CLUSTER_ARRIVE();   // releases peer h stores; consumed at next step's il==2
    }

    CLUSTER_WAIT();    // drain final phase; peer remote stores complete before exit

    // final h (T even -> hst0); each CTA stores its own column half
    for (int idx = tid; idx < RWS * 128; idx += PTH) {
        const int r = idx >> 7, l = idx & 127;
        g_hT[(r0 + r) * H_ + q * 128 + l] = hst0[(q * 128 + l) * HSTR + r];
    }
}

// ---------------------------------------------------------------- out = elu((sum_c hT) @ Wf + bf)
__global__ void __launch_bounds__(128) k_out(const float* __restrict__ Wf,
                                             const float* __restrict__ bf,
                                             float* __restrict__ out) {
    __shared__ float s[H_];
    const int b = blockIdx.x;
    const int tid = threadIdx.x;
    for (int k = tid; k < H_; k += 128)
        s[k] = g_hT[b * H_ + k] + g_hT[B_ * H_ + b * H_ + k] + g_hT[2 * B_ * H_ + b * H_ + k];
    __syncthreads();
    float acc = bf[tid];
#pragma unroll 8
    for (int k = 0; k < H_; k++)
        acc = fmaf(s[k], Wf[k * OUT_ + tid], acc);
    out[b * OUT_ + tid] = acc > 0.0f ? acc : expm1f(acc);
}

// ---------------------------------------------------------------- feature = mean_b hT -> (3, H)
__global__ void __launch_bounds__(256) k_feat(float* __restrict__ feat) {
    __shared__ float p[8][32];
    const int tx = threadIdx.x & 31, ty = threadIdx.x >> 5;
    const int jg = blockIdx.x * 32 + tx;            // 0..767
    const int c = jg >> 8, j = jg & 255;
    float s = 0.0f;
#pragma unroll 8
    for (int i = 0; i < 32; i++) {
        const int b = ty * 32 + i;
        s += g_hT[c * (B_ * H_) + b * H_ + j];
    }
    p[ty][tx] = s;
    __syncthreads();
    if (ty == 0) {
        float acc = 0.0f;
#pragma unroll
        for (int qq = 0; qq < 8; qq++) acc += p[qq][tx];
        feat[jg] = acc * (1.0f / 256.0f);
    }
}

// ---------------------------------------------------------------- launch
extern "C" void kernel_launch(void* const* d_in, const int* in_sizes, int n_in,
                              void* d_out, int out_size) {
    const float* x  = (const float*)d_in[0];
    const float* h0 = (const float*)d_in[1];
    const float* Wx = (const float*)d_in[2];
    const float* bx = (const float*)d_in[3];
    const float* Wh = (const float*)d_in[4];
    const float* bh = (const float*)d_in[5];
    const float* Wf = (const float*)d_in[6];
    const float* bf = (const float*)d_in[7];
    float* out = (float*)d_out;

    cudaFuncSetAttribute(k_cru, cudaFuncAttributeMaxDynamicSharedMemorySize, SMEM_BYTES);

    dim3 gp(WH2_HALF / 256, 2);          // (384, 2)
    k_prep<<<gp, 256>>>(Wh);
    dim3 g1(H3_ / 64, (T_ * B_) / 64);   // (12, 512)
    k_gx<<<g1, 256>>>(x, Wx, bx);
    k_cru<<<NBLK, PTH, SMEM_BYTES>>>(h0, bh);
    k_out<<<B_, 128>>>(Wf, bf, out);
    k_feat<<<24, 256>>>(out + (out_size - 3 * H_));
}